// round 1
// baseline (speedup 1.0000x reference)
#include <cuda_runtime.h>
#include <cuda_bf16.h>
#include <cstdint>

// CrossPatchModule closed form:
//   B=4, C=64, H=W=512, PH=PW=8, PN=64, kh=kw=64
//   ph=h>>6, i=h&63, pw=w>>6, j=w&63
//   s = ph*8+pw;  m=(c+s)&63
//   out[b,c,h,w] = x[b,c, (m>>3)*64 + i, (m&7)*64 + j] + abs_pos[c*64+m]
//
// Pure permutation gather + scalar add. Both source and destination accesses
// are contiguous 256B spans per 64-col block -> fully coalesced float4.

__global__ __launch_bounds__(256, 8)
void crosspatch_kernel(const float4* __restrict__ x,
                       const float*  __restrict__ ap,
                       float4*       __restrict__ out)
{
    // One float4 per thread. Total float4 = 4*64*512*512/4 = 16,777,216.
    // Linear layout: t = ((b*64 + c)*512 + h)*128 + w4
    unsigned t = blockIdx.x * 256u + threadIdx.x;

    unsigned w4 = t & 127u;          // float4 index within row (128 per row)
    unsigned h  = (t >> 7) & 511u;
    unsigned c  = (t >> 16) & 63u;
    unsigned b  = t >> 22;

    unsigned pw = w4 >> 4;           // 16 float4 per 64-col block
    unsigned j4 = w4 & 15u;
    unsigned ph = h >> 6;
    unsigned i  = h & 63u;

    unsigned s = ph * 8u + pw;
    unsigned m = (c + s) & 63u;

    unsigned src_h  = ((m >> 3) << 6) | i;         // (m/8)*64 + i
    unsigned src_w4 = ((m & 7u) << 4) | j4;        // ((m%8)*64)/4 + j4

    // per-(b,c) image = 512*512 floats = 65536 float4
    unsigned base = ((b << 6) | c) << 16;

    float4 v = x[base + (src_h << 7) + src_w4];
    float  a = __ldg(&ap[(c << 6) | m]);

    v.x += a; v.y += a; v.z += a; v.w += a;
    out[t] = v;
}

extern "C" void kernel_launch(void* const* d_in, const int* in_sizes, int n_in,
                              void* d_out, int out_size)
{
    const float4* x  = (const float4*)d_in[0];   // (4,64,512,512) fp32
    const float*  ap = (const float*)d_in[1];    // (1,1,64,64,1,1) fp32
    float4*       out = (float4*)d_out;

    // 16,777,216 float4 / 256 threads = 65,536 blocks
    crosspatch_kernel<<<65536, 256>>>(x, ap, out);
}

// round 2
// speedup vs baseline: 1.0289x; 1.0289x over previous
#include <cuda_runtime.h>
#include <cuda_bf16.h>
#include <cstdint>

// CrossPatchModule closed form:
//   B=4, C=64, H=W=512, PH=PW=8, PN=64, kh=kw=64
//   ph=h>>6, i=h&63, pw=w>>6, j=w&63
//   s = ph*8+pw;  m=(c+s)&63
//   out[b,c,h,w] = x[b,c, (m>>3)*64 + i, (m&7)*64 + j] + abs_pos[c*64+m]
//
// Pure permutation gather + scalar add; 512MB irreducible traffic.
// R1: 4 independent float4 per thread (MLP=4, front-batched) + streaming
// load/store hints (no L2 reuse exists).

__global__ __launch_bounds__(256, 8)
void crosspatch_kernel(const float4* __restrict__ x,
                       const float*  __restrict__ ap,
                       float4*       __restrict__ out)
{
    // Each thread handles 4 float4, stride 256 between them (warp stays
    // coalesced: 32 consecutive float4 per access).
    // Total float4 = 16,777,216 -> 16384 blocks * 256 threads * 4.
    unsigned t0 = blockIdx.x * 1024u + threadIdx.x;

    unsigned src[4];
    float    add[4];
    unsigned dst[4];

#pragma unroll
    for (int k = 0; k < 4; ++k) {
        unsigned t  = t0 + k * 256u;
        unsigned w4 = t & 127u;          // float4 index within row
        unsigned h  = (t >> 7) & 511u;
        unsigned c  = (t >> 16) & 63u;
        unsigned b  = t >> 22;

        unsigned pw = w4 >> 4;
        unsigned j4 = w4 & 15u;
        unsigned ph = h >> 6;
        unsigned i  = h & 63u;

        unsigned s = ph * 8u + pw;
        unsigned m = (c + s) & 63u;

        unsigned src_h  = ((m >> 3) << 6) | i;
        unsigned src_w4 = ((m & 7u) << 4) | j4;
        unsigned base   = ((b << 6) | c) << 16;   // 65536 float4 per image

        src[k] = base + (src_h << 7) + src_w4;
        dst[k] = t;
        add[k] = __ldg(&ap[(c << 6) | m]);
    }

    float4 v[4];
#pragma unroll
    for (int k = 0; k < 4; ++k)
        v[k] = __ldcs(&x[src[k]]);       // evict-first: no reuse, don't thrash L2

#pragma unroll
    for (int k = 0; k < 4; ++k) {
        float a = add[k];
        v[k].x += a; v[k].y += a; v[k].z += a; v[k].w += a;
        __stcs(&out[dst[k]], v[k]);
    }
}

extern "C" void kernel_launch(void* const* d_in, const int* in_sizes, int n_in,
                              void* d_out, int out_size)
{
    const float4* x  = (const float4*)d_in[0];   // (4,64,512,512) fp32
    const float*  ap = (const float*)d_in[1];    // (1,1,64,64,1,1) fp32
    float4*       out = (float4*)d_out;

    crosspatch_kernel<<<16384, 256>>>(x, ap, out);
}